// round 17
// baseline (speedup 1.0000x reference)
#include <cuda_runtime.h>
#include <math.h>

#define BB    32
#define NN    4096
#define HH    256
#define NNZC  65536
#define PP    128                // chunks per batch
#define CHUNK 32                 // rows per block (8 warps x 4 rows)

// ---------------- scratch (no cudaMalloc allowed) ----------------
__device__ unsigned char g_validb[BB * NN];   // 0/1 byte mask
__device__ float g_scores[BB * NN];           // masked scores (-inf)
__device__ float g_pm[BB * PP];               // per-chunk max
__device__ float g_pz[BB * PP];               // per-chunk sum exp
__device__ float g_pacc[BB * PP * HH];        // per-chunk weighted x sum
__device__ float g_m[BB];
__device__ float g_z[BB];

// ---------------- kernels ----------------

__global__ void k_zero() {
    int i = blockIdx.x * blockDim.x + threadIdx.x;
    ((uint4*)g_validb)[i] = make_uint4(0u, 0u, 0u, 0u);
}

// Scatter valid mask; detect int64 vs int32 index dtype on device.
__global__ void k_scatter(const void* __restrict__ bp,
                          const void* __restrict__ rp) {
    __shared__ int s_is64;
    if (threadIdx.x == 0) {
        const unsigned long long* b64 = (const unsigned long long*)bp;
        int ok = 1;
        #pragma unroll
        for (int i = 0; i < 8; i++)
            if (b64[i] >= (unsigned long long)BB) ok = 0;
        s_is64 = ok;
    }
    __syncthreads();
    int i = blockIdx.x * blockDim.x + threadIdx.x;
    int bi, ri;
    if (s_is64) {
        bi = (int)((const long long*)bp)[i];
        ri = (int)((const long long*)rp)[i];
    } else {
        bi = ((const int*)bp)[i];
        ri = ((const int*)rp)[i];
    }
    g_validb[bi * NN + ri] = 1;
}

// Main: one block per (chunk, batch); 8 warps x 4 rows. Rows live in
// registers end-to-end: front-batched loads -> interleaved dot reduce ->
// block max -> weighted accumulation from registers. x read exactly once.
__global__ void __launch_bounds__(256, 3)
k_main(const float* __restrict__ x, const float* __restrict__ W,
       const float* __restrict__ bptr) {
    int b = blockIdx.y, p = blockIdx.x;
    int t = threadIdx.x, w = t >> 5, lane = t & 31;

    __shared__ float s_acc[8][HH];      // 8 KB warp partial outputs
    __shared__ float red[8], red2[8];
    __shared__ float ss2;

    // W1 in registers: lane covers cols [lane*4,+4) and [128+lane*4,+4)
    float4 wa = *(const float4*)(W + lane * 4);
    float4 wc = *(const float4*)(W + 128 + lane * 4);
    float bias = *bptr;

    int row0 = p * CHUNK + w * 4;
    const float* rp = x + ((size_t)b * NN + row0) * HH + lane * 4;

    // ---- front-batched loads: 8 LDG.128, no dependent stalls between ----
    float4 R[4], C[4];
    #pragma unroll
    for (int r = 0; r < 4; r++) {
        R[r] = *(const float4*)(rp + (size_t)r * HH);
        C[r] = *(const float4*)(rp + (size_t)r * HH + 128);
    }

    float pd[4];
    #pragma unroll
    for (int r = 0; r < 4; r++)
        pd[r] = R[r].x * wa.x + R[r].y * wa.y + R[r].z * wa.z + R[r].w * wa.w
              + C[r].x * wc.x + C[r].y * wc.y + C[r].z * wc.z + C[r].w * wc.w;

    // warp 0 also computes s2 = dot(x[b,0,:], W[H:2H])
    float pd2 = 0.f;
    if (w == 0) {
        const float* r0 = x + (size_t)b * NN * HH + lane * 4;
        float4 A2  = *(const float4*)(r0);
        float4 C2  = *(const float4*)(r0 + 128);
        float4 v2a = *(const float4*)(W + HH + lane * 4);
        float4 v2c = *(const float4*)(W + HH + 128 + lane * 4);
        pd2 = A2.x * v2a.x + A2.y * v2a.y + A2.z * v2a.z + A2.w * v2a.w
            + C2.x * v2c.x + C2.y * v2c.y + C2.z * v2c.z + C2.w * v2c.w;
    }

    // 5 interleaved shuffle-reduce trees
    #pragma unroll
    for (int o = 16; o > 0; o >>= 1) {
        #pragma unroll
        for (int r = 0; r < 4; r++)
            pd[r] += __shfl_xor_sync(0xffffffffu, pd[r], o);
        pd2 += __shfl_xor_sync(0xffffffffu, pd2, o);
    }
    if (w == 0 && lane == 0) ss2 = pd2;

    // validity of this warp's 4 consecutive rows: one u32 load
    unsigned int v4 = *(const unsigned int*)(g_validb + b * NN + row0);

    __syncthreads();
    float s2 = ss2;

    // ---- scores + chunk max ----
    float e[4], me = -INFINITY;
    #pragma unroll
    for (int r = 0; r < 4; r++) {
        int v = (int)((v4 >> (8 * r)) & 1u);
        float tot = pd[r] + bias + (v ? s2 : 0.f);
        // invalid -> -inf; valid with exact 0 -> -inf (masked_fill(==0))
        e[r] = (v && tot != 0.f) ? tot : -INFINITY;
        me = fmaxf(me, e[r]);
    }
    if (lane == 0) {
        *(float4*)&g_scores[b * NN + row0] = make_float4(e[0], e[1], e[2], e[3]);
        red[w] = me;
    }
    __syncthreads();

    float M = red[0];
    #pragma unroll
    for (int i = 1; i < 8; i++) M = fmaxf(M, red[i]);

    // ---- weights + weighted accumulation from registers ----
    float wv[4], zw = 0.f;
    #pragma unroll
    for (int r = 0; r < 4; r++) {
        wv[r] = (e[r] == -INFINITY) ? 0.f : __expf(e[r] - M);
        zw += wv[r];
    }
    float a0 = 0.f, a1 = 0.f, a2 = 0.f, a3 = 0.f;
    float a4 = 0.f, a5 = 0.f, a6 = 0.f, a7 = 0.f;
    #pragma unroll
    for (int r = 0; r < 4; r++) {
        a0 += wv[r] * R[r].x; a1 += wv[r] * R[r].y;
        a2 += wv[r] * R[r].z; a3 += wv[r] * R[r].w;
        a4 += wv[r] * C[r].x; a5 += wv[r] * C[r].y;
        a6 += wv[r] * C[r].z; a7 += wv[r] * C[r].w;
    }
    *(float4*)&s_acc[w][lane * 4]       = make_float4(a0, a1, a2, a3);
    *(float4*)&s_acc[w][128 + lane * 4] = make_float4(a4, a5, a6, a7);
    if (lane == 0) red2[w] = zw;
    __syncthreads();

    // ---- combine 8 warp partials; write chunk partials ----
    float a = 0.f;
    #pragma unroll
    for (int i = 0; i < 8; i++) a += s_acc[i][t];
    g_pacc[(size_t)(b * PP + p) * HH + t] = a;

    if (t == 0) {
        float Z = 0.f;
        #pragma unroll
        for (int i = 0; i < 8; i++) Z += red2[i];
        g_pm[b * PP + p] = M;
        g_pz[b * PP + p] = Z;
    }
}

// Per-batch softmax stats: one warp per batch (1 block, 1024 threads).
__global__ void k_stats() {
    int b = threadIdx.x >> 5, lane = threadIdx.x & 31;
    float pm[4], pz[4];
    float m = -INFINITY;
    #pragma unroll
    for (int k = 0; k < 4; k++) {
        pm[k] = g_pm[b * PP + lane + k * 32];
        pz[k] = g_pz[b * PP + lane + k * 32];
        m = fmaxf(m, pm[k]);
    }
    #pragma unroll
    for (int o = 16; o > 0; o >>= 1)
        m = fmaxf(m, __shfl_xor_sync(0xffffffffu, m, o));
    float z = 0.f;
    #pragma unroll
    for (int k = 0; k < 4; k++)
        z += (pm[k] == -INFINITY) ? 0.f : pz[k] * __expf(pm[k] - m);
    #pragma unroll
    for (int o = 16; o > 0; o >>= 1)
        z += __shfl_xor_sync(0xffffffffu, z, o);
    if (lane == 0) { g_m[b] = m; g_z[b] = z; }
}

// out[b,col] = (sum_q pacc[b,q,col]*sf[q]) / z
__global__ void __launch_bounds__(128)
k_out(float* __restrict__ out) {
    int b = blockIdx.y;
    int col = blockIdx.x * 128 + threadIdx.x;
    __shared__ float sf[PP];
    float m = g_m[b];
    float pmv = g_pm[b * PP + threadIdx.x];
    sf[threadIdx.x] = (pmv == -INFINITY) ? 0.f : __expf(pmv - m);
    __syncthreads();
    const float* pa = g_pacc + (size_t)b * PP * HH + col;
    float o = 0.f;
    #pragma unroll 8
    for (int q = 0; q < PP; q++)
        o += pa[(size_t)q * HH] * sf[q];
    out[b * HH + col] = o / g_z[b];
}

// attn[b,n] = exp(score - m_b) / Z_b   (-inf -> 0)
__global__ void k_attn(float* __restrict__ attn) {
    int i = blockIdx.x * blockDim.x + threadIdx.x;
    int b = i >> 12;   // N = 4096
    float s = g_scores[i];
    attn[i] = (s == -INFINITY) ? 0.f : __expf(s - g_m[b]) / g_z[b];
}

// ---------------- launch ----------------
extern "C" void kernel_launch(void* const* d_in, const int* in_sizes, int n_in,
                              void* d_out, int out_size) {
    const float* x    = (const float*)d_in[0];
    const void*  bi   = d_in[1];
    const void*  ri   = d_in[2];
    const float* W    = (const float*)d_in[3];
    const float* bptr = (const float*)d_in[4];
    float* out = (float*)d_out;

    k_zero   <<<(BB * NN) / 16 / 256, 256>>>();
    k_scatter<<<NNZC / 256, 256>>>(bi, ri);
    k_main   <<<dim3(PP, BB), 256>>>(x, W, bptr);
    k_stats  <<<1, 1024>>>();
    k_out    <<<dim3(2, BB), 128>>>(out);
    if (out_size >= BB * HH + BB * NN)
        k_attn<<<(BB * NN) / 256, 256>>>(out + BB * HH);
}